// round 9
// baseline (speedup 1.0000x reference)
#include <cuda_runtime.h>
#include <math.h>

#define Lr 1024
#define Br 32
#define Dr 256
#define LAMf 0.2f
#define NR (Lr*Br)

// Scratch (device globals, zero-initialized). Batch-major r = b*Lr + i.
__device__ float g_K[NR*5];      // K[i, j=i+d-2], d=0..4
__device__ float g_S[NR];        // row sums of K
__device__ float g_E[NR];        // sum_d K*(1-cos)
__device__ int   g_cnt[Br];      // per-batch arrival counters (self-resetting)

// One kernel: band compute (4096 batch-pure blocks of 8 rows) + last-block epilogue per batch.
__global__ void __launch_bounds__(256) kall(const float* __restrict__ m1,
                                            const float* __restrict__ m2,
                                            const int* __restrict__ lengths,
                                            float* __restrict__ out) {
    __shared__ float sh_invn[20];    // [0,8): 1/||x_{i0+k}||, [8,20): 1/||y_{i0-2+k}||
    __shared__ int   sh_last;
    __shared__ float sh_K[Lr*5];     // epilogue staging (last block per batch only)
    __shared__ float sh_invS[Lr];
    __shared__ float sh_t[Lr];
    __shared__ float sh_c[256];

    int tid  = threadIdx.x;
    int w    = tid >> 5, lane = tid & 31;
    int b    = blockIdx.x & 31;
    int i0   = (blockIdx.x >> 5) * 8;
    int l    = __ldg(lengths + b);
    int base = b * Lr;

    // ---- phase 1: inverse norms, 20 jobs in one 3-value batched butterfly per warp ----
    {
        float ss[3];
        #pragma unroll
        for (int k = 0; k < 3; k++) {
            int job = w + k*8;
            float s = 0.0f;
            if (job < 20) {
                int row; const float* src;
                if (job < 8) { row = i0 + job;           src = m1; }
                else         { row = i0 - 2 + (job - 8); src = m2; }
                if (row >= 0 && row < l) {
                    const float4* p = (const float4*)(src + ((size_t)(row*Br + b)) * Dr);
                    float4 a = p[lane], c = p[lane + 32];
                    s = a.x*a.x + a.y*a.y + a.z*a.z + a.w*a.w
                      + c.x*c.x + c.y*c.y + c.z*c.z + c.w*c.w;
                }
            }
            ss[k] = s;
        }
        #pragma unroll
        for (int o = 16; o; o >>= 1) {
            #pragma unroll
            for (int k = 0; k < 3; k++) ss[k] += __shfl_xor_sync(0xffffffffu, ss[k], o);
        }
        if (lane == 0) {
            #pragma unroll
            for (int k = 0; k < 3; k++) {
                int job = w + k*8;
                if (job < 20)
                    sh_invn[job] = (ss[k] > 0.0f) ? (1.0f / fmaxf(sqrtf(ss[k]), 1e-5f)) : 0.0f;
            }
        }
    }
    __syncthreads();

    // ---- phase 2: 5 band dots per row, batched butterfly ----
    int i = i0 + w;
    bool writer = false;
    if (i < l) {
        const float4* xp = (const float4*)(m1 + ((size_t)(i*Br + b)) * Dr);
        float4 xa = xp[lane], xb = xp[lane + 32];
        float dots[5];
        #pragma unroll
        for (int d = 0; d < 5; d++) {
            int j = i + d - 2;
            float acc = 0.0f;
            if (j >= 0 && j < l) {
                const float4* yp = (const float4*)(m2 + ((size_t)(j*Br + b)) * Dr);
                float4 ya = yp[lane], yb = yp[lane + 32];
                acc = xa.x*ya.x + xa.y*ya.y + xa.z*ya.z + xa.w*ya.w
                    + xb.x*yb.x + xb.y*yb.y + xb.z*yb.z + xb.w*yb.w;
            }
            dots[d] = acc;
        }
        #pragma unroll
        for (int o = 16; o; o >>= 1) {
            #pragma unroll
            for (int d = 0; d < 5; d++)
                dots[d] += __shfl_xor_sync(0xffffffffu, dots[d], o);
        }
        if (lane == 0) {
            float invnx = sh_invn[w];
            float S = 0.0f, E = 0.0f, Ks[5];
            #pragma unroll
            for (int d = 0; d < 5; d++) {
                int j = i + d - 2;
                float Kv = 0.0f;
                if (j >= 0 && j < l) {
                    float Mv = 1.0f - dots[d] * invnx * sh_invn[8 + w + d];
                    Kv = expf(-LAMf * Mv);
                    E += Kv * Mv;
                }
                Ks[d] = Kv; S += Kv;
            }
            int rr = base + i;
            g_S[rr] = S; g_E[rr] = E;
            #pragma unroll
            for (int d = 0; d < 5; d++) g_K[rr*5 + d] = Ks[d];
            writer = true;
        }
    }

    // ---- release by writer lanes only, then one arrival atomic ----
    if (writer || (lane == 0 && i >= l)) __threadfence();
    __syncthreads();
    if (tid == 0) {
        int old = atomicAdd(&g_cnt[b], 1);
        sh_last = (old == 127);
        if (old == 127) g_cnt[b] = 0;      // self-reset for graph replay
    }
    __syncthreads();
    if (!sh_last) return;
    __threadfence();                        // acquire (last block per batch only)

    // ---- epilogue: whole batch b, smem-staged ----
    {
        const float* Ksrc = g_K + (size_t)base * 5;
        for (int idx = tid; idx < Lr*5; idx += 256) sh_K[idx] = Ksrc[idx];
        for (int idx = tid; idx < Lr; idx += 256)
            sh_invS[idx] = 1.0f / g_S[base + idx];
    }
    __syncthreads();

    for (int j = tid; j < Lr; j += 256) {
        float t = 1.0f;
        if (j < l) {
            t = 0.0f;
            #pragma unroll
            for (int dd = 0; dd < 5; dd++) {
                int ii = j + dd - 2;
                if (ii >= 0 && ii < l)
                    t += sh_K[ii*5 + (4 - dd)] * sh_invS[ii];
            }
        }
        sh_t[j] = t;
    }
    __syncthreads();

    float acc = 0.0f;
    for (int j = tid; j < l; j += 256) {
        float inv = sh_invS[j] / sh_t[j];
        acc += g_E[base + j] * inv;
        float* Po = out + (size_t)b * Lr * Lr + (size_t)j * Lr;
        #pragma unroll
        for (int d = 0; d < 5; d++) {
            int jj = j + d - 2;
            if (jj >= 0 && jj < l)
                Po[jj] = sh_K[j*5 + d] * sh_t[jj] * inv;
        }
    }
    sh_c[tid] = acc;
    __syncthreads();
    #pragma unroll
    for (int s = 128; s; s >>= 1) {
        if (tid < s) sh_c[tid] += sh_c[tid + s];
        __syncthreads();
    }
    if (tid == 0) out[(size_t)Br * Lr * Lr + b] = sh_c[0] / (float)l;
}

extern "C" void kernel_launch(void* const* d_in, const int* in_sizes, int n_in,
                              void* d_out, int out_size) {
    const float* m1      = (const float*)d_in[0];
    const float* m2      = (const float*)d_in[1];
    const int*   lengths = (const int*)d_in[2];
    float* out = (float*)d_out;

    kall<<<Br*128, 256>>>(m1, m2, lengths, out);
}

// round 10
// speedup vs baseline: 1.1565x; 1.1565x over previous
#include <cuda_runtime.h>
#include <math.h>

#define Lr 1024
#define Br 32
#define Dr 256
#define LAMf 0.2f

#define TILE 16          // output rows per block
#define NDOT 24          // TILE + 8  (dot rows: halo ±4)
#define NY   28          // TILE + 12 (y-norm rows: halo ±6)
#define NT   20          // TILE + 4  (t values: halo ±2)
#define NTILES 64        // Lr / TILE
#define NBLK (NTILES*Br) // 2048

__device__ float g_cpart[NBLK];   // per-block cost partials (deterministic writes)

// Self-sufficient band block: norms + dots for tile+halo, t in-block, P band + cost partial.
__global__ void __launch_bounds__(256) kband2(const float* __restrict__ m1,
                                              const float* __restrict__ m2,
                                              const int* __restrict__ lengths,
                                              float* __restrict__ out) {
    __shared__ float sh_invnx[NDOT];
    __shared__ float sh_invny[NY];
    __shared__ float sh_K[NDOT*5];
    __shared__ float sh_invS[NDOT];
    __shared__ float sh_E[NDOT];
    __shared__ float sh_t[NT];
    __shared__ float sh_cp[TILE];

    int tid  = threadIdx.x;
    int w    = tid >> 5, lane = tid & 31;
    int bid  = blockIdx.x;
    int b    = bid & 31;
    int i0   = (bid >> 5) * TILE;
    int l    = __ldg(lengths + b);
    int h    = i0 - 4;    // dot-row base
    int hy   = i0 - 6;    // y-norm base

    // ---- phase 1: 52 inverse norms (24 x + 28 y), 7-way batched butterfly per warp ----
    {
        float ss[7];
        #pragma unroll
        for (int k = 0; k < 7; k++) {
            int job = w + k*8;
            float s = 0.0f;
            if (job < NDOT + NY) {
                int row; const float* src;
                if (job < NDOT) { row = h  + job;        src = m1; }
                else            { row = hy + job - NDOT; src = m2; }
                if (row >= 0 && row < l) {
                    const float4* p = (const float4*)(src + ((size_t)(row*Br + b)) * Dr);
                    float4 a = p[lane], c = p[lane + 32];
                    s = a.x*a.x + a.y*a.y + a.z*a.z + a.w*a.w
                      + c.x*c.x + c.y*c.y + c.z*c.z + c.w*c.w;
                }
            }
            ss[k] = s;
        }
        #pragma unroll
        for (int o = 16; o; o >>= 1)
            #pragma unroll
            for (int k = 0; k < 7; k++) ss[k] += __shfl_xor_sync(0xffffffffu, ss[k], o);
        if (lane == 0) {
            #pragma unroll
            for (int k = 0; k < 7; k++) {
                int job = w + k*8;
                float invn = (ss[k] > 0.0f) ? (1.0f / fmaxf(sqrtf(ss[k]), 1e-5f)) : 0.0f;
                if (job < NDOT)            sh_invnx[job] = invn;
                else if (job < NDOT + NY)  sh_invny[job - NDOT] = invn;
            }
        }
    }
    __syncthreads();

    // ---- phase 2: dots for 24 rows (3 per warp: k = w, w+8, w+16), 15-way butterfly ----
    {
        float acc[15];
        float4 xs[3][2];
        #pragma unroll
        for (int rr = 0; rr < 3; rr++) {
            int i = h + w + rr*8;
            if (i >= 0 && i < l) {
                const float4* xp = (const float4*)(m1 + ((size_t)(i*Br + b)) * Dr);
                xs[rr][0] = xp[lane]; xs[rr][1] = xp[lane + 32];
            } else {
                xs[rr][0] = xs[rr][1] = make_float4(0.f,0.f,0.f,0.f);
            }
            #pragma unroll
            for (int d = 0; d < 5; d++) {
                int j = i + d - 2;
                float a = 0.0f;
                if (i >= 0 && i < l && j >= 0 && j < l) {
                    const float4* yp = (const float4*)(m2 + ((size_t)(j*Br + b)) * Dr);
                    float4 ya = yp[lane], yb = yp[lane + 32];
                    a = xs[rr][0].x*ya.x + xs[rr][0].y*ya.y + xs[rr][0].z*ya.z + xs[rr][0].w*ya.w
                      + xs[rr][1].x*yb.x + xs[rr][1].y*yb.y + xs[rr][1].z*yb.z + xs[rr][1].w*yb.w;
                }
                acc[rr*5 + d] = a;
            }
        }
        #pragma unroll
        for (int o = 16; o; o >>= 1)
            #pragma unroll
            for (int q = 0; q < 15; q++) acc[q] += __shfl_xor_sync(0xffffffffu, acc[q], o);

        if (lane == 0) {
            #pragma unroll
            for (int rr = 0; rr < 3; rr++) {
                int k = w + rr*8;
                int i = h + k;
                float S = 0.0f, E = 0.0f;
                float invnx = sh_invnx[k];
                #pragma unroll
                for (int d = 0; d < 5; d++) {
                    int j = i + d - 2;
                    float Kv = 0.0f;
                    if (i >= 0 && i < l && j >= 0 && j < l) {
                        float Mv = 1.0f - acc[rr*5+d] * invnx * sh_invny[k + d];
                        Kv = expf(-LAMf * Mv);
                        E += Kv * Mv;
                    }
                    sh_K[k*5 + d] = Kv;
                    S += Kv;
                }
                sh_invS[k] = (S > 0.0f) ? (1.0f / S) : 0.0f;
                sh_E[k] = E;
            }
        }
    }
    __syncthreads();

    // ---- phase 3: t[j] for j in [i0-2, i0+TILE+2) ----
    if (tid < NT) {
        int j = i0 - 2 + tid;
        float t = 1.0f;
        if (j >= 0 && j < l) {
            t = 0.0f;
            #pragma unroll
            for (int dd = 0; dd < 5; dd++) {
                int i = j + dd - 2;                // = h + (tid + dd)
                if (i >= 0 && i < l)
                    t += sh_K[(tid + dd)*5 + (4 - dd)] * sh_invS[tid + dd];
            }
        }
        sh_t[tid] = t;
    }
    __syncthreads();

    // ---- phase 4: P band scatter + cost partial for own 16 rows ----
    if (tid < TILE) {
        int i = i0 + tid;
        float cp = 0.0f;
        if (i < l) {
            int k = tid + 4;
            float invS = sh_invS[k];
            float rt   = 1.0f / sh_t[tid + 2];
            float inv  = invS * rt;
            cp = sh_E[k] * inv / (float)l;
            float* Po = out + (size_t)b * Lr * Lr + (size_t)i * Lr;
            #pragma unroll
            for (int d = 0; d < 5; d++) {
                int jj = i + d - 2;
                if (jj >= 0 && jj < l)
                    Po[jj] = sh_K[k*5 + d] * sh_t[tid + d] * inv;
            }
        }
        sh_cp[tid] = cp;
    }
    __syncthreads();
    if (tid == 0) {
        float s = 0.0f;
        #pragma unroll
        for (int k = 0; k < TILE; k++) s += sh_cp[k];
        g_cpart[bid] = s;
    }
}

// Fold 64 tile-partials per batch into the cost slot (deterministic tree).
__global__ void kcost2(float* __restrict__ out) {
    __shared__ float sh[64];
    int b = blockIdx.x, tid = threadIdx.x;
    sh[tid] = g_cpart[(size_t)tid * Br + b];    // bid = tile*32 + b
    __syncthreads();
    #pragma unroll
    for (int s = 32; s; s >>= 1) {
        if (tid < s) sh[tid] += sh[tid + s];
        __syncthreads();
    }
    if (tid == 0) out[(size_t)Br * Lr * Lr + b] = sh[0];
}

extern "C" void kernel_launch(void* const* d_in, const int* in_sizes, int n_in,
                              void* d_out, int out_size) {
    const float* m1      = (const float*)d_in[0];
    const float* m2      = (const float*)d_in[1];
    const int*   lengths = (const int*)d_in[2];
    float* out = (float*)d_out;

    kband2<<<NBLK, 256>>>(m1, m2, lengths, out);   // self-sufficient tiles, no sync machinery
    kcost2<<<Br, 64>>>(out);                        // tiny deterministic fold
}

// round 11
// speedup vs baseline: 1.4515x; 1.2551x over previous
#include <cuda_runtime.h>
#include <math.h>

#define Lr 1024
#define Br 32
#define Dr 256
#define LAMf 0.2f
#define NR (Lr*Br)

// Scratch (device globals, zero-initialized). Batch-major r = b*Lr + i.
__device__ float g_K[NR*5];      // K[i, j=i+d-2], d=0..4
__device__ float g_invS[NR];     // 1 / row sum of K
__device__ float g_E[NR];        // sum_d K*(1-cos)

// ---------------------------------------------------------------- band kernel
// grid = 2048 batch-pure blocks of 512 threads; block = (batch b, 16 rows).
// Phase 1: 36 shared inverse norms (16 x-rows + 20 y-rows), 3-wide batched butterfly.
// Phase 2: warp per row, 5 band dots, one 5-wide butterfly, no yy trees.
__global__ void __launch_bounds__(512) kband(const float* __restrict__ m1,
                                             const float* __restrict__ m2,
                                             const int* __restrict__ lengths) {
    __shared__ float sh_invnx[16];   // 1/||x_{i0+k}||
    __shared__ float sh_invny[20];   // 1/||y_{i0-2+k}||

    int tid  = threadIdx.x;
    int w    = tid >> 5, lane = tid & 31;
    int b    = blockIdx.x & 31;
    int i0   = (blockIdx.x >> 5) * 16;
    int l    = __ldg(lengths + b);
    int base = b * Lr;

    // ---- phase 1: 36 norm jobs over 16 warps (w, w+16, w+32 for w<4) ----
    {
        float ss[3];
        #pragma unroll
        for (int k = 0; k < 3; k++) {
            int job = w + k*16;
            float s = 0.0f;
            if (job < 36) {
                int row; const float* src;
                if (job < 16) { row = i0 + job;            src = m1; }
                else          { row = i0 - 2 + (job - 16); src = m2; }
                if (row >= 0 && row < l) {
                    const float4* p = (const float4*)(src + ((size_t)(row*Br + b)) * Dr);
                    float4 a = p[lane], c = p[lane + 32];
                    s = a.x*a.x + a.y*a.y + a.z*a.z + a.w*a.w
                      + c.x*c.x + c.y*c.y + c.z*c.z + c.w*c.w;
                }
            }
            ss[k] = s;
        }
        #pragma unroll
        for (int o = 16; o; o >>= 1) {
            #pragma unroll
            for (int k = 0; k < 3; k++) ss[k] += __shfl_xor_sync(0xffffffffu, ss[k], o);
        }
        if (lane == 0) {
            #pragma unroll
            for (int k = 0; k < 3; k++) {
                int job = w + k*16;
                if (job < 36) {
                    float invn = (ss[k] > 0.0f) ? (1.0f / fmaxf(sqrtf(ss[k]), 1e-5f)) : 0.0f;
                    if (job < 16) sh_invnx[job] = invn;
                    else          sh_invny[job - 16] = invn;
                }
            }
        }
    }
    __syncthreads();

    // ---- phase 2: warp w owns row i = i0 + w ----
    int i = i0 + w;
    if (i >= l) return;
    const float4* xp = (const float4*)(m1 + ((size_t)(i*Br + b)) * Dr);
    float4 xa = xp[lane], xb = xp[lane + 32];
    float dots[5];
    #pragma unroll
    for (int d = 0; d < 5; d++) {
        int j = i + d - 2;
        float acc = 0.0f;
        if (j >= 0 && j < l) {
            const float4* yp = (const float4*)(m2 + ((size_t)(j*Br + b)) * Dr);
            float4 ya = yp[lane], yb = yp[lane + 32];
            acc = xa.x*ya.x + xa.y*ya.y + xa.z*ya.z + xa.w*ya.w
                + xb.x*yb.x + xb.y*yb.y + xb.z*yb.z + xb.w*yb.w;
        }
        dots[d] = acc;
    }
    #pragma unroll
    for (int o = 16; o; o >>= 1) {
        #pragma unroll
        for (int d = 0; d < 5; d++)
            dots[d] += __shfl_xor_sync(0xffffffffu, dots[d], o);
    }
    if (lane == 0) {
        float invnx = sh_invnx[w];
        float S = 0.0f, E = 0.0f, Ks[5];
        #pragma unroll
        for (int d = 0; d < 5; d++) {
            int j = i + d - 2;
            float Kv = 0.0f;
            if (j >= 0 && j < l) {
                float Mv = 1.0f - dots[d] * invnx * sh_invny[w + d];  // y idx = j-(i0-2) = w+d
                Kv = __expf(-LAMf * Mv);
                E += Kv * Mv;
            }
            Ks[d] = Kv; S += Kv;
        }
        int rr = base + i;
        g_invS[rr] = 1.0f / S;
        g_E[rr] = E;
        #pragma unroll
        for (int d = 0; d < 5; d++) g_K[rr*5 + d] = Ks[d];
    }
}

// ---------------------------------------------------------------- t + cost + band scatter
// Block per batch (proven R4 version), smem-staged, invS pre-reciprocal.
__global__ void __launch_bounds__(1024) ktc(const int* __restrict__ lengths,
                                            float* __restrict__ out) {
    __shared__ float sh_K[Lr*5];
    __shared__ float sh_invS[Lr];
    __shared__ float sh_t[Lr];
    __shared__ float sh_c[Lr];
    int b = blockIdx.x;
    int j = threadIdx.x;
    int l = lengths[b];
    int base = b * Lr;

    {
        const float4* Ksrc = (const float4*)(g_K + (size_t)base * 5);
        float4* Kdst = (float4*)sh_K;
        #pragma unroll
        for (int k = 0; k < 2; k++)
            if (j + k*1024 < Lr*5/4) Kdst[j + k*1024] = Ksrc[j + k*1024];
        if (j < Lr/4)
            ((float4*)sh_invS)[j] = ((const float4*)(g_invS + base))[j];
    }
    __syncthreads();

    float t = 1.0f, term = 0.0f;
    if (j < l) {
        t = 0.0f;
        #pragma unroll
        for (int dd = 0; dd < 5; dd++) {
            int i = j + dd - 2;
            if (i >= 0 && i < l)
                t += sh_K[i*5 + (4 - dd)] * sh_invS[i];   // d = j-i+2 = 4-dd
        }
        term = g_E[base + j] * sh_invS[j] / ((float)l * t);
    }
    sh_t[j] = t;
    sh_c[j] = term;
    __syncthreads();

    if (j < l) {
        float inv = sh_invS[j] / sh_t[j];
        float* Po = out + (size_t)b * Lr * Lr + (size_t)j * Lr;
        #pragma unroll
        for (int d = 0; d < 5; d++) {
            int jj = j + d - 2;
            if (jj >= 0 && jj < l)
                Po[jj] = sh_K[j*5 + d] * sh_t[jj] * inv;
        }
    }

    #pragma unroll
    for (int s = 512; s; s >>= 1) {
        if (j < s) sh_c[j] += sh_c[j + s];
        __syncthreads();
    }
    if (j == 0) out[(size_t)Br * Lr * Lr + b] = sh_c[0];
}

extern "C" void kernel_launch(void* const* d_in, const int* in_sizes, int n_in,
                              void* d_out, int out_size) {
    const float* m1      = (const float*)d_in[0];
    const float* m2      = (const float*)d_in[1];
    const int*   lengths = (const int*)d_in[2];
    float* out = (float*)d_out;

    kband<<<Br*64, 512>>>(m1, m2, lengths);   // batch-pure blocks, shared norms
    ktc<<<Br, 1024>>>(lengths, out);          // per-batch t + cost + band scatter
}

// round 12
// speedup vs baseline: 1.4779x; 1.0182x over previous
#include <cuda_runtime.h>
#include <math.h>

#define Lr 1024
#define Br 32
#define Dr 256
#define LAMf 0.2f
#define NR (Lr*Br)

// Scratch (device globals, zero-initialized). Batch-major r = b*Lr + i.
__device__ float g_Kn[NR*5];     // K[i,d] * invS[i]   (row-normalized band kernel)
__device__ float g_En[NR];       // E[i]  * invS[i]

typedef unsigned long long u64;

__device__ __forceinline__ u64 ffma2(u64 a, u64 b, u64 c) {
    u64 d;
    asm("fma.rn.f32x2 %0, %1, %2, %3;" : "=l"(d) : "l"(a), "l"(b), "l"(c));
    return d;
}
__device__ __forceinline__ float unpack_sum(u64 a) {
    float2 f = *reinterpret_cast<float2*>(&a);
    return f.x + f.y;
}

// ---------------------------------------------------------------- band kernel
// 2048 batch-pure blocks x 512 threads; block = (batch b, 16 rows).
// Phase 1: 20 y inverse norms (packed FMA). Phase 2: warp/row, 5 dots + x-norm
// in one 6-wide butterfly, packed FMA throughout.
__global__ void __launch_bounds__(512) kband(const float* __restrict__ m1,
                                             const float* __restrict__ m2,
                                             const int* __restrict__ lengths) {
    __shared__ float sh_invny[20];   // 1/||y_{i0-2+k}||

    int tid  = threadIdx.x;
    int w    = tid >> 5, lane = tid & 31;
    int b    = blockIdx.x & 31;
    int i0   = (blockIdx.x >> 5) * 16;
    int l    = __ldg(lengths + b);
    int base = b * Lr;

    // ---- phase 1: 20 y-norm jobs over 16 warps (jobs w, w+16) ----
    {
        float ss[2];
        #pragma unroll
        for (int k = 0; k < 2; k++) {
            int job = w + k*16;
            u64 acc = 0ull;
            if (job < 20) {
                int row = i0 - 2 + job;
                if (row >= 0 && row < l) {
                    const ulonglong2* p = (const ulonglong2*)(m2 + ((size_t)(row*Br + b)) * Dr);
                    ulonglong2 a = p[lane], c = p[lane + 32];
                    acc = ffma2(a.x, a.x, acc);
                    acc = ffma2(a.y, a.y, acc);
                    acc = ffma2(c.x, c.x, acc);
                    acc = ffma2(c.y, c.y, acc);
                }
            }
            ss[k] = unpack_sum(acc);
        }
        #pragma unroll
        for (int o = 16; o; o >>= 1) {
            #pragma unroll
            for (int k = 0; k < 2; k++) ss[k] += __shfl_xor_sync(0xffffffffu, ss[k], o);
        }
        if (lane == 0) {
            #pragma unroll
            for (int k = 0; k < 2; k++) {
                int job = w + k*16;
                if (job < 20)
                    sh_invny[job] = (ss[k] > 0.0f) ? (1.0f / fmaxf(sqrtf(ss[k]), 1e-5f)) : 0.0f;
            }
        }
    }
    __syncthreads();

    // ---- phase 2: warp w owns row i = i0 + w ----
    int i = i0 + w;
    if (i >= l) return;
    const ulonglong2* xp = (const ulonglong2*)(m1 + ((size_t)(i*Br + b)) * Dr);
    ulonglong2 xa = xp[lane], xb = xp[lane + 32];

    u64 pacc[6];
    pacc[0] = ffma2(xa.x, xa.x, 0ull);            // xx
    pacc[0] = ffma2(xa.y, xa.y, pacc[0]);
    pacc[0] = ffma2(xb.x, xb.x, pacc[0]);
    pacc[0] = ffma2(xb.y, xb.y, pacc[0]);
    #pragma unroll
    for (int d = 0; d < 5; d++) {
        int j = i + d - 2;
        u64 acc = 0ull;
        if (j >= 0 && j < l) {
            const ulonglong2* yp = (const ulonglong2*)(m2 + ((size_t)(j*Br + b)) * Dr);
            ulonglong2 ya = yp[lane], yb = yp[lane + 32];
            acc = ffma2(xa.x, ya.x, acc);
            acc = ffma2(xa.y, ya.y, acc);
            acc = ffma2(xb.x, yb.x, acc);
            acc = ffma2(xb.y, yb.y, acc);
        }
        pacc[d + 1] = acc;
    }
    float s[6];
    #pragma unroll
    for (int q = 0; q < 6; q++) s[q] = unpack_sum(pacc[q]);
    #pragma unroll
    for (int o = 16; o; o >>= 1) {
        #pragma unroll
        for (int q = 0; q < 6; q++) s[q] += __shfl_xor_sync(0xffffffffu, s[q], o);
    }
    if (lane == 0) {
        float invnx = 1.0f / fmaxf(sqrtf(s[0]), 1e-5f);
        float S = 0.0f, E = 0.0f, Ks[5];
        #pragma unroll
        for (int d = 0; d < 5; d++) {
            int j = i + d - 2;
            float Kv = 0.0f;
            if (j >= 0 && j < l) {
                float Mv = 1.0f - s[d+1] * invnx * sh_invny[w + d];  // y idx = j-(i0-2) = w+d
                Kv = __expf(-LAMf * Mv);
                E += Kv * Mv;
            }
            Ks[d] = Kv; S += Kv;
        }
        float invS = 1.0f / S;
        int rr = base + i;
        g_En[rr] = E * invS;
        #pragma unroll
        for (int d = 0; d < 5; d++) g_Kn[rr*5 + d] = Ks[d] * invS;
    }
}

// ---------------------------------------------------------------- t + cost + band scatter
// Block per batch; stage Kn only (20 KB); t[j] = pure 5-term smem sum.
__global__ void __launch_bounds__(1024) ktc(const int* __restrict__ lengths,
                                            float* __restrict__ out) {
    __shared__ float sh_K[Lr*5];
    __shared__ float sh_t[Lr];
    __shared__ float sh_c[Lr];
    int b = blockIdx.x;
    int j = threadIdx.x;
    int l = lengths[b];
    int base = b * Lr;

    float Ev = g_En[base + j];                       // prefetch (zero for rows >= l)
    {
        const float4* Ksrc = (const float4*)(g_Kn + (size_t)base * 5);
        float4* Kdst = (float4*)sh_K;
        #pragma unroll
        for (int k = 0; k < 2; k++)
            if (j + k*1024 < Lr*5/4) Kdst[j + k*1024] = Ksrc[j + k*1024];
    }
    __syncthreads();

    float t = 1.0f, term = 0.0f;
    if (j < l) {
        t = 0.0f;
        #pragma unroll
        for (int dd = 0; dd < 5; dd++) {
            int i = j + dd - 2;
            if (i >= 0 && i < l)
                t += sh_K[i*5 + (4 - dd)];           // Kn already includes invS
        }
        term = Ev / ((float)l * t);
    }
    sh_t[j] = t;
    sh_c[j] = term;
    __syncthreads();

    if (j < l) {
        float rt = 1.0f / sh_t[j];
        float* Po = out + (size_t)b * Lr * Lr + (size_t)j * Lr;
        #pragma unroll
        for (int d = 0; d < 5; d++) {
            int jj = j + d - 2;
            if (jj >= 0 && jj < l)
                Po[jj] = sh_K[j*5 + d] * sh_t[jj] * rt;
        }
    }

    #pragma unroll
    for (int s = 512; s; s >>= 1) {
        if (j < s) sh_c[j] += sh_c[j + s];
        __syncthreads();
    }
    if (j == 0) out[(size_t)Br * Lr * Lr + b] = sh_c[0];
}

extern "C" void kernel_launch(void* const* d_in, const int* in_sizes, int n_in,
                              void* d_out, int out_size) {
    const float* m1      = (const float*)d_in[0];
    const float* m2      = (const float*)d_in[1];
    const int*   lengths = (const int*)d_in[2];
    float* out = (float*)d_out;

    kband<<<Br*64, 512>>>(m1, m2, lengths);   // packed-FMA band, shared y-norms
    ktc<<<Br, 1024>>>(lengths, out);          // slim t + cost + band scatter
}